// round 14
// baseline (speedup 1.0000x reference)
#include <cuda_runtime.h>
#include <cuda_fp16.h>

// Problem constants (H=4 heads, D=32 dims -> 128 halves / node row = 256B)
#define HH 4
#define DD 32
#define ROW 128
#define MAX_N 65536
#define MAX_E 1700000

// Scratch (__device__ globals; no allocation allowed)
__device__ __half g_qh[(size_t)MAX_N * ROW];   // fp16 Q premultiplied by beta/sqrt(D)
__device__ __half g_kh[(size_t)MAX_N * ROW];   // fp16 K
__device__ float  g_s[MAX_N * HH];             // per (node, head) sum of exp
__device__ int    g_cnt[MAX_N];                // edges per destination node
__device__ int    g_start[MAX_N];              // range start per node
__device__ int    g_cursor[MAX_N];             // scatter cursor per node
__device__ int    g_su[MAX_E];                 // source node ids, grouped by dest
__device__ int    g_total;                     // global range allocator
__device__ float  g_coef;                      // lam / beta
__device__ float  g_qscale;                    // beta / sqrt(D)
__device__ float  g_eA[HH];                    // exp(beta * a_h)

// Zero accumulators/counters + output; thread 0 computes the scalar params.
__global__ void k_init(const float* __restrict__ lr, const float* __restrict__ br,
                       const float* __restrict__ a,
                       float* __restrict__ out, int N, int nh, int gh) {
    int i = blockIdx.x * blockDim.x + threadIdx.x;
    if (i < nh) g_s[i] = 0.0f;
    else if (i < nh + gh) out[i - nh] = 0.0f;
    if (i < N) g_cnt[i] = 0;
    if (i == 0) {
        g_total = 0;
        float l = lr[0], b = br[0];
        float sp_l = (l > 20.f) ? l : log1pf(expf(l));
        float sp_b = (b > 20.f) ? b : log1pf(expf(b));
        float beta = fminf(sp_b, 10.0f);
        g_coef = sp_l / beta;
        g_qscale = beta * 0.17677669529663687f;   // beta / sqrt(32)
        for (int h = 0; h < HH; h++) g_eA[h] = expf(beta * a[h]);
    }
}

// Streaming fp32 -> fp16 (Q scaled by beta/sqrt(D)), fused with the
// destination histogram (same thread count: nvec = N*32, E ~ N*32).
__global__ void k_convert_hist(const float* __restrict__ Q, const float* __restrict__ K,
                               const int* __restrict__ c2, int nvec, int E) {
    int i = blockIdx.x * blockDim.x + threadIdx.x;
    if (i < nvec) {
        float qs = g_qscale;
        float4 q = __ldg((const float4*)Q + i);
        float4 k = __ldg((const float4*)K + i);
        __half2* qo = (__half2*)g_qh;
        __half2* ko = (__half2*)g_kh;
        qo[2 * i]     = __floats2half2_rn(q.x * qs, q.y * qs);
        qo[2 * i + 1] = __floats2half2_rn(q.z * qs, q.w * qs);
        ko[2 * i]     = __floats2half2_rn(k.x, k.y);
        ko[2 * i + 1] = __floats2half2_rn(k.z, k.w);
    }
    if (i < E) atomicAdd(&g_cnt[__ldg(c2 + i)], 1);
}

// Per-node contiguous range allocation (order across nodes irrelevant -> no scan).
__global__ void k_offsets(int N) {
    int n = blockIdx.x * blockDim.x + threadIdx.x;
    if (n >= N) return;
    int cnt = g_cnt[n];
    int start = atomicAdd(&g_total, cnt);
    g_start[n] = start;
    g_cursor[n] = start;
}

// Scatter source ids into destination-grouped order.
__global__ void k_scatter(const int* __restrict__ c2, const int* __restrict__ u2, int E) {
    int e = blockIdx.x * blockDim.x + threadIdx.x;
    if (e >= E) return;
    int c = __ldg(c2 + e);
    int pos = atomicAdd(&g_cursor[c], 1);
    g_su[pos] = __ldg(u2 + e);
}

// dot(q,k) over this lane's 8 dims -> reduce across the 4 lanes of the head -> exp.
// mask4 = the 4-lane subgroup mask (all 4 lanes share the same node/loop count).
__device__ __forceinline__ float edot(uint4 qr, uint4 kr, unsigned mask4) {
    const __half2* qa = (const __half2*)&qr;
    const __half2* ka = (const __half2*)&kr;
    __half2 p0 = __hmul2(qa[0], ka[0]);
    __half2 p1 = __hmul2(qa[1], ka[1]);
    __half2 p2 = __hmul2(qa[2], ka[2]);
    __half2 p3 = __hmul2(qa[3], ka[3]);
    __half2 s = __hadd2(__hadd2(p0, p1), __hadd2(p2, p3));
    float2 f = __half22float2(s);
    float dot = f.x + f.y;
    dot += __shfl_xor_sync(mask4, dot, 2);
    dot += __shfl_xor_sync(mask4, dot, 1);
    return __expf(dot);
}

// One 16-lane group per destination node. Q row loaded ONCE; K rows streamed
// with 4-way unrolling (MLP). Register accumulation -> single store, no atomics.
__global__ void __launch_bounds__(256) k_edges_sorted(int N) {
    int t = blockIdx.x * blockDim.x + threadIdx.x;
    int n = t >> 4;
    if (n >= N) return;
    int l16 = t & 15;
    int lane = threadIdx.x & 31;
    unsigned mask4 = 0xFu << (lane & 28);

    int start = g_start[n];
    int cnt   = g_cnt[n];

    const uint4* Qv = (const uint4*)g_qh;
    const uint4* Kv = (const uint4*)g_kh;
    uint4 qr = Qv[(size_t)n * 16 + l16];

    float acc = 0.0f;
    int i = 0;
    for (; i + 4 <= cnt; i += 4) {
        int u0 = __ldg(g_su + start + i);
        int u1 = __ldg(g_su + start + i + 1);
        int u2 = __ldg(g_su + start + i + 2);
        int u3 = __ldg(g_su + start + i + 3);
        uint4 k0 = Kv[(size_t)u0 * 16 + l16];
        uint4 k1 = Kv[(size_t)u1 * 16 + l16];
        uint4 k2 = Kv[(size_t)u2 * 16 + l16];
        uint4 k3 = Kv[(size_t)u3 * 16 + l16];
        acc += edot(qr, k0, mask4);
        acc += edot(qr, k1, mask4);
        acc += edot(qr, k2, mask4);
        acc += edot(qr, k3, mask4);
    }
    for (; i < cnt; i++) {
        int u = __ldg(g_su + start + i);
        uint4 kr = Kv[(size_t)u * 16 + l16];
        acc += edot(qr, kr, mask4);
    }

    if ((l16 & 3) == 0) {
        int h = l16 >> 2;
        g_s[n * HH + h] = acc * g_eA[h];   // exp(beta*a_h) factored out of the sum
    }
}

// Per-node lse = log(s) -> shared G*H bins -> global atomics.
// Grid-stride with few blocks; batch is sorted so bins are concentrated.
__global__ void k_final(const int* __restrict__ batch, float* __restrict__ out,
                        int NH, int gh) {
    extern __shared__ float bins[];
    for (int t = threadIdx.x; t < gh; t += blockDim.x) bins[t] = 0.0f;
    __syncthreads();

    float coef = g_coef;
    for (int idx = blockIdx.x * blockDim.x + threadIdx.x; idx < NH;
         idx += gridDim.x * blockDim.x) {
        float s = g_s[idx];
        if (s > 0.0f) {
            int n = idx >> 2;            // HH == 4
            int h = idx & 3;
            atomicAdd(&bins[__ldg(batch + n) * HH + h], coef * __logf(s));
        }
    }
    __syncthreads();
    for (int t = threadIdx.x; t < gh; t += blockDim.x) {
        float v = bins[t];
        if (v != 0.0f) atomicAdd(out + t, v);
    }
}

extern "C" void kernel_launch(void* const* d_in, const int* in_sizes, int n_in,
                              void* d_out, int out_size) {
    // metadata order: G[0], Q2[1], K2[2], a_2[3], lambda_2_raw[4], beta_2_raw[5],
    //                 c_2[6], u_2[7], batch[8]
    const float* Q  = (const float*)d_in[1];
    const float* K  = (const float*)d_in[2];
    const float* a  = (const float*)d_in[3];
    const float* lr = (const float*)d_in[4];
    const float* br = (const float*)d_in[5];
    const int* c2   = (const int*)d_in[6];
    const int* u2   = (const int*)d_in[7];
    const int* bat  = (const int*)d_in[8];

    int E  = in_sizes[6];
    int N  = in_sizes[8];
    int gh = out_size;            // num_graphs * H
    int nh = N * HH;
    float* out = (float*)d_out;

    k_init<<<(nh + gh + 255) / 256, 256>>>(lr, br, a, out, N, nh, gh);

    int nvec = N * ROW / 4;       // N*32
    int big = nvec > E ? nvec : E;
    k_convert_hist<<<(big + 255) / 256, 256>>>(Q, K, c2, nvec, E);

    k_offsets<<<(N + 255) / 256, 256>>>(N);
    k_scatter<<<(E + 255) / 256, 256>>>(c2, u2, E);

    long long tot = (long long)N * 16;
    k_edges_sorted<<<(unsigned)((tot + 255) / 256), 256>>>(N);

    k_final<<<296, 256, gh * sizeof(float)>>>(bat, out, nh, gh);
}